// round 2
// baseline (speedup 1.0000x reference)
#include <cuda_runtime.h>
#include <math_constants.h>

#define BB 4096
#define DD 2048
#define PP 256
#define SS 64
#define CC 32
#define KP 8

// ---------------- scratch (device globals; no allocation) ----------------
__device__ float g_logits[BB * PP];                 // 4 MB
__device__ int   g_topidx[BB * KP];
__device__ int   g_child[BB * KP];
__device__ float g_G[(size_t)PP * DD * CC];         // 64 MB  [p][d][c]
__device__ float g_M[(size_t)PP * CC * DD];         // 64 MB  [p][c][d]
__device__ int   g_count[PP];
__device__ int   g_offset[PP];
__device__ int   g_cursor[PP];
__device__ int   g_pairs[BB * KP];
__device__ float g_WrdT[(size_t)PP * DD];           // 2 MB  [p][d]

// ---------------- zero counters ----------------
__global__ void k_zero() {
    if (threadIdx.x < PP) g_count[threadIdx.x] = 0;
}

// ---------------- parent logits: [B,P] = x @ W_re^T + b_re (fp32 SGEMM) ----------------
__global__ void k_gemm_logits(const float* __restrict__ X,
                              const float* __restrict__ Wre,
                              const float* __restrict__ bre) {
    __shared__ float As[64][17];
    __shared__ float Bs[64][17];
    const int tid = threadIdx.x;
    const int n0 = blockIdx.x * 64;
    const int m0 = blockIdx.y * 64;
    const int tx = tid & 15, ty = tid >> 4;
    const int lr = tid >> 2;
    const int lc = (tid & 3) << 2;
    float acc[4][4];
#pragma unroll
    for (int i = 0; i < 4; i++)
#pragma unroll
        for (int j = 0; j < 4; j++) acc[i][j] = 0.f;

    for (int k0 = 0; k0 < DD; k0 += 16) {
        float4 av = *(const float4*)&X[(size_t)(m0 + lr) * DD + k0 + lc];
        float4 bv = *(const float4*)&Wre[(size_t)(n0 + lr) * DD + k0 + lc];
        As[lr][lc] = av.x; As[lr][lc + 1] = av.y; As[lr][lc + 2] = av.z; As[lr][lc + 3] = av.w;
        Bs[lr][lc] = bv.x; Bs[lr][lc + 1] = bv.y; Bs[lr][lc + 2] = bv.z; Bs[lr][lc + 3] = bv.w;
        __syncthreads();
#pragma unroll
        for (int k = 0; k < 16; k++) {
            float a[4], b[4];
#pragma unroll
            for (int i = 0; i < 4; i++) a[i] = As[ty * 4 + i][k];
#pragma unroll
            for (int j = 0; j < 4; j++) b[j] = Bs[tx * 4 + j][k];
#pragma unroll
            for (int i = 0; i < 4; i++)
#pragma unroll
                for (int j = 0; j < 4; j++) acc[i][j] += a[i] * b[j];
        }
        __syncthreads();
    }
#pragma unroll
    for (int i = 0; i < 4; i++) {
#pragma unroll
        for (int j = 0; j < 4; j++) {
            int n = n0 + tx * 4 + j;
            g_logits[(size_t)(m0 + ty * 4 + i) * PP + n] = acc[i][j] + bre[n];
        }
    }
}

// ---------------- top-8 per token (warp per token, tie -> lower index) ----------------
__global__ void k_topk() {
    int gw = (blockIdx.x * blockDim.x + threadIdx.x) >> 5;
    int lane = threadIdx.x & 31;
    if (gw >= BB) return;
    const float* lg = g_logits + (size_t)gw * PP;
    float v[8];
    int id[8];
#pragma unroll
    for (int j = 0; j < 8; j++) {
        int p = j * 32 + lane;
        v[j] = lg[p];
        id[j] = p;
    }
    for (int it = 0; it < KP; it++) {
        float bv = v[0];
        int bi = id[0];
#pragma unroll
        for (int j = 1; j < 8; j++) {
            if (v[j] > bv || (v[j] == bv && id[j] < bi)) { bv = v[j]; bi = id[j]; }
        }
#pragma unroll
        for (int off = 16; off >= 1; off >>= 1) {
            float ov = __shfl_down_sync(0xffffffffu, bv, off);
            int   oi = __shfl_down_sync(0xffffffffu, bi, off);
            if (ov > bv || (ov == bv && oi < bi)) { bv = ov; bi = oi; }
        }
        bi = __shfl_sync(0xffffffffu, bi, 0);
        if (lane == 0) {
            g_topidx[gw * KP + it] = bi;
            atomicAdd(&g_count[bi], 1);
        }
#pragma unroll
        for (int j = 0; j < 8; j++)
            if (id[j] == bi) v[j] = -CUDART_INF_F;
    }
}

// ---------------- exclusive scan of counts (single block) ----------------
__global__ void k_scan() {
    __shared__ int s[PP];
    int t = threadIdx.x;
    int c = g_count[t];
    s[t] = c;
    __syncthreads();
    for (int off = 1; off < PP; off <<= 1) {
        int v = (t >= off) ? s[t - off] : 0;
        __syncthreads();
        s[t] += v;
        __syncthreads();
    }
    int excl = s[t] - c;
    g_offset[t] = excl;
    g_cursor[t] = excl;
}

// ---------------- scatter (b,k) pairs into per-parent buckets ----------------
__global__ void k_scatter() {
    int i = blockIdx.x * 256 + threadIdx.x;
    int p = g_topidx[i];
    int pos = atomicAdd(&g_cursor[p], 1);
    g_pairs[pos] = i;
}

// ---------------- G[p] = W_ce[p] @ W_down[p], stored [p][d][c] ----------------
__global__ void k_precompG(const float* __restrict__ Wdown,
                           const float* __restrict__ Wce) {
    __shared__ float Wd[SS * 64];    // [s][dl]   (broadcast access -> no pad)
    __shared__ float Ce[CC * 65];    // [c][s]    padded
    int p = blockIdx.x;
    int d0 = blockIdx.y * 64;
    int tid = threadIdx.x;
    for (int l = tid; l < SS * 64; l += 256) {
        int s = l >> 6, dl = l & 63;
        Wd[s * 64 + dl] = Wdown[((size_t)p * SS + s) * DD + d0 + dl];
    }
    for (int l = tid; l < CC * SS; l += 256) {
        int c = l >> 6, s = l & 63;
        Ce[c * 65 + s] = Wce[((size_t)p * CC + c) * SS + s];
    }
    __syncthreads();
    int c = tid & 31;
    int dl0 = tid >> 5;
    float acc[8];
#pragma unroll
    for (int j = 0; j < 8; j++) acc[j] = 0.f;
    for (int s = 0; s < SS; s++) {
        float wce = Ce[c * 65 + s];
#pragma unroll
        for (int j = 0; j < 8; j++) acc[j] += wce * Wd[s * 64 + dl0 + 8 * j];
    }
#pragma unroll
    for (int j = 0; j < 8; j++)
        g_G[((size_t)p * DD + d0 + dl0 + 8 * j) * CC + c] = acc[j];
}

// ---------------- M[p] = W_up[p] @ W_cd[p], stored [p][c][d] ----------------
__global__ void k_precompM(const float* __restrict__ Wup,
                           const float* __restrict__ Wcd) {
    __shared__ float Wu[64 * 65];   // [dl][s] padded
    __shared__ float Cd[SS * 33];   // [s][c]  padded
    int p = blockIdx.x;
    int d0 = blockIdx.y * 64;
    int tid = threadIdx.x;
    for (int l = tid; l < 64 * SS; l += 256) {
        int dl = l >> 6, s = l & 63;
        Wu[dl * 65 + s] = Wup[((size_t)p * DD + d0 + dl) * SS + s];
    }
    for (int l = tid; l < SS * CC; l += 256) {
        int s = l >> 5, c = l & 31;
        Cd[s * 33 + c] = Wcd[((size_t)p * SS + s) * CC + c];
    }
    __syncthreads();
    int w = tid >> 5, lane = tid & 31;
    float acc[2][4];
#pragma unroll
    for (int j = 0; j < 2; j++)
#pragma unroll
        for (int cc = 0; cc < 4; cc++) acc[j][cc] = 0.f;
    for (int s = 0; s < SS; s++) {
        float wu0 = Wu[lane * 65 + s];
        float wu1 = Wu[(lane + 32) * 65 + s];
#pragma unroll
        for (int cc = 0; cc < 4; cc++) {
            float wc = Cd[s * 33 + (w << 2) + cc];
            acc[0][cc] += wu0 * wc;
            acc[1][cc] += wu1 * wc;
        }
    }
#pragma unroll
    for (int j = 0; j < 2; j++)
#pragma unroll
        for (int cc = 0; cc < 4; cc++)
            g_M[((size_t)p * CC + (w << 2) + cc) * DD + d0 + lane + 32 * j] = acc[j][cc];
}

// ---------------- transpose W_rd [D,P] -> [P,D] for coalesced decode ----------------
__global__ void k_transpose(const float* __restrict__ Wrd) {
    __shared__ float tile[32][33];
    int p0 = blockIdx.x * 32;
    int d0 = blockIdx.y * 32;
    int tx = threadIdx.x & 31, ty = threadIdx.x >> 5;
    for (int r = ty; r < 32; r += 8)
        tile[r][tx] = Wrd[(size_t)(d0 + r) * PP + p0 + tx];
    __syncthreads();
    for (int r = ty; r < 32; r += 8)
        g_WrdT[(size_t)(p0 + r) * DD + d0 + tx] = tile[tx][r];
}

// ---------------- per-parent child logits + argmax ----------------
// block.x = parent, block.y in [0,2) strides token tiles of 64
__global__ void k_childlogits(const float* __restrict__ X,
                              const float* __restrict__ bce) {
    __shared__ float Xs[64 * 65];   // [t][d] padded
    __shared__ float Gs[64 * 33];   // [d][c] padded
    __shared__ int toks[64];
    int p = blockIdx.x;
    int base = g_offset[p];
    int n = g_count[p];
    int tid = threadIdx.x;
    int chalf = tid & 15;
    int cbase = chalf << 1;         // this thread's two child columns
    int trow = tid >> 4;            // 0..15
    float bc0 = bce[p * CC + cbase];
    float bc1 = bce[p * CC + cbase + 1];

    for (int t0 = blockIdx.y * 64; t0 < n; t0 += 128) {
        if (tid < 64) toks[tid] = (t0 + tid < n) ? g_pairs[base + t0 + tid] : -1;
        __syncthreads();

        float acc[4][2];
#pragma unroll
        for (int j = 0; j < 4; j++) { acc[j][0] = 0.f; acc[j][1] = 0.f; }

        for (int d0 = 0; d0 < DD; d0 += 64) {
            const float* gp = g_G + ((size_t)p * DD + d0) * CC;
            for (int l = tid; l < 64 * CC; l += 256)
                Gs[(l >> 5) * 33 + (l & 31)] = gp[l];
            for (int l = tid; l < 64 * 64; l += 256) {
                int r = l >> 6, cidx = l & 63;
                int pi = toks[r];
                Xs[r * 65 + cidx] = (pi >= 0) ? X[(size_t)(pi >> 3) * DD + d0 + cidx] : 0.f;
            }
            __syncthreads();
#pragma unroll 4
            for (int d = 0; d < 64; d++) {
                float g0 = Gs[d * 33 + cbase];
                float g1 = Gs[d * 33 + cbase + 1];
#pragma unroll
                for (int j = 0; j < 4; j++) {
                    float xv = Xs[(trow + 16 * j) * 65 + d];
                    acc[j][0] += xv * g0;
                    acc[j][1] += xv * g1;
                }
            }
            __syncthreads();
        }

#pragma unroll
        for (int j = 0; j < 4; j++) {
            float v0 = acc[j][0] + bc0;
            float v1 = acc[j][1] + bc1;
            float bv; int bi;
            if (v1 > v0) { bv = v1; bi = cbase + 1; }
            else         { bv = v0; bi = cbase; }
#pragma unroll
            for (int off = 8; off >= 1; off >>= 1) {
                float ov = __shfl_down_sync(0xffffffffu, bv, off, 16);
                int   oi = __shfl_down_sync(0xffffffffu, bi, off, 16);
                if (ov > bv || (ov == bv && oi < bi)) { bv = ov; bi = oi; }
            }
            if (chalf == 0) {
                int t = trow + 16 * j;
                int pi = toks[t];
                if (pi >= 0) g_child[pi] = bi;
            }
        }
        __syncthreads();
    }
}

// ---------------- decode: out = bias + 0.1*sum W_rd cols + sum M[p][c] ----------------
__global__ void k_decode(const float* __restrict__ dbias, float* __restrict__ out) {
    int b = blockIdx.x;
    __shared__ int sp[KP], sc[KP];
    int tid = threadIdx.x;
    if (tid < KP) {
        sp[tid] = g_topidx[b * KP + tid];
        sc[tid] = g_child[b * KP + tid];
    }
    __syncthreads();
#pragma unroll
    for (int jj = 0; jj < 8; jj++) {
        int d = tid + jj * 256;
        float a = dbias[d];
#pragma unroll
        for (int k = 0; k < KP; k++) {
            int p = sp[k], c = sc[k];
            a += 0.1f * g_WrdT[(size_t)p * DD + d] + g_M[((size_t)p * CC + c) * DD + d];
        }
        out[(size_t)b * DD + d] = a;
    }
}

// ---------------- launch ----------------
extern "C" void kernel_launch(void* const* d_in, const int* in_sizes, int n_in,
                              void* d_out, int out_size) {
    const float* x      = (const float*)d_in[0];
    const float* W_re   = (const float*)d_in[1];
    const float* b_re   = (const float*)d_in[2];
    const float* W_rd   = (const float*)d_in[3];
    const float* W_down = (const float*)d_in[4];
    const float* W_up   = (const float*)d_in[5];
    const float* W_ce   = (const float*)d_in[6];
    const float* b_ce   = (const float*)d_in[7];
    const float* W_cd   = (const float*)d_in[8];
    const float* dbias  = (const float*)d_in[9];
    float* out = (float*)d_out;

    k_zero<<<1, 256>>>();
    k_gemm_logits<<<dim3(PP / 64, BB / 64), 256>>>(x, W_re, b_re);
    k_precompG<<<dim3(PP, DD / 64), 256>>>(W_down, W_ce);
    k_precompM<<<dim3(PP, DD / 64), 256>>>(W_up, W_cd);
    k_transpose<<<dim3(PP / 32, DD / 32), 256>>>(W_rd);
    k_topk<<<(BB * 32) / 256, 256>>>();
    k_scan<<<1, 256>>>();
    k_scatter<<<(BB * KP) / 256, 256>>>();
    k_childlogits<<<dim3(PP, 2), 256>>>(x, b_ce);
    k_decode<<<BB, 256>>>(dbias, out);
}

// round 3
// speedup vs baseline: 1.0899x; 1.0899x over previous
#include <cuda_runtime.h>
#include <math_constants.h>

#define BB 4096
#define DD 2048
#define PP 256
#define SS 64
#define CC 32
#define KP 8

// ---------------- scratch (device globals; no allocation) ----------------
__device__ float g_logits[BB * PP];                 // 4 MB
__device__ int   g_topidx[BB * KP];
__device__ int   g_child[BB * KP];
__device__ float g_G[(size_t)PP * CC * DD];         // 64 MB  [p][c][d]
__device__ float g_M[(size_t)PP * CC * DD];         // 64 MB  [p][c][d]  (includes 0.1*W_rd col)
__device__ int   g_count[PP];
__device__ int   g_offset[PP];
__device__ int   g_cursor[PP];
__device__ int   g_pairs[BB * KP];

// ---------------- zero counters ----------------
__global__ void k_zero() {
    if (threadIdx.x < PP) g_count[threadIdx.x] = 0;
}

// ---------------- parent logits: [B,P] = x @ W_re^T + b_re (fp32 SGEMM) ----------------
__global__ void k_gemm_logits(const float* __restrict__ X,
                              const float* __restrict__ Wre,
                              const float* __restrict__ bre) {
    __shared__ float As[64][17];
    __shared__ float Bs[64][17];
    const int tid = threadIdx.x;
    const int n0 = blockIdx.x * 64;
    const int m0 = blockIdx.y * 64;
    const int tx = tid & 15, ty = tid >> 4;
    const int lr = tid >> 2;
    const int lc = (tid & 3) << 2;
    float acc[4][4];
#pragma unroll
    for (int i = 0; i < 4; i++)
#pragma unroll
        for (int j = 0; j < 4; j++) acc[i][j] = 0.f;

    for (int k0 = 0; k0 < DD; k0 += 16) {
        float4 av = *(const float4*)&X[(size_t)(m0 + lr) * DD + k0 + lc];
        float4 bv = *(const float4*)&Wre[(size_t)(n0 + lr) * DD + k0 + lc];
        As[lr][lc] = av.x; As[lr][lc + 1] = av.y; As[lr][lc + 2] = av.z; As[lr][lc + 3] = av.w;
        Bs[lr][lc] = bv.x; Bs[lr][lc + 1] = bv.y; Bs[lr][lc + 2] = bv.z; Bs[lr][lc + 3] = bv.w;
        __syncthreads();
#pragma unroll
        for (int k = 0; k < 16; k++) {
            float a[4], b[4];
#pragma unroll
            for (int i = 0; i < 4; i++) a[i] = As[ty * 4 + i][k];
#pragma unroll
            for (int j = 0; j < 4; j++) b[j] = Bs[tx * 4 + j][k];
#pragma unroll
            for (int i = 0; i < 4; i++)
#pragma unroll
                for (int j = 0; j < 4; j++) acc[i][j] += a[i] * b[j];
        }
        __syncthreads();
    }
#pragma unroll
    for (int i = 0; i < 4; i++) {
#pragma unroll
        for (int j = 0; j < 4; j++) {
            int n = n0 + tx * 4 + j;
            g_logits[(size_t)(m0 + ty * 4 + i) * PP + n] = acc[i][j] + bre[n];
        }
    }
}

// ---------------- top-8 per token (warp per token, tie -> lower index) ----------------
__global__ void k_topk() {
    int gw = (blockIdx.x * blockDim.x + threadIdx.x) >> 5;
    int lane = threadIdx.x & 31;
    if (gw >= BB) return;
    const float* lg = g_logits + (size_t)gw * PP;
    float v[8];
    int id[8];
#pragma unroll
    for (int j = 0; j < 8; j++) {
        int p = j * 32 + lane;
        v[j] = lg[p];
        id[j] = p;
    }
    for (int it = 0; it < KP; it++) {
        float bv = v[0];
        int bi = id[0];
#pragma unroll
        for (int j = 1; j < 8; j++) {
            if (v[j] > bv || (v[j] == bv && id[j] < bi)) { bv = v[j]; bi = id[j]; }
        }
#pragma unroll
        for (int off = 16; off >= 1; off >>= 1) {
            float ov = __shfl_down_sync(0xffffffffu, bv, off);
            int   oi = __shfl_down_sync(0xffffffffu, bi, off);
            if (ov > bv || (ov == bv && oi < bi)) { bv = ov; bi = oi; }
        }
        bi = __shfl_sync(0xffffffffu, bi, 0);
        if (lane == 0) {
            g_topidx[gw * KP + it] = bi;
            atomicAdd(&g_count[bi], 1);
        }
#pragma unroll
        for (int j = 0; j < 8; j++)
            if (id[j] == bi) v[j] = -CUDART_INF_F;
    }
}

// ---------------- exclusive scan of counts (single block) ----------------
__global__ void k_scan() {
    __shared__ int s[PP];
    int t = threadIdx.x;
    int c = g_count[t];
    s[t] = c;
    __syncthreads();
    for (int off = 1; off < PP; off <<= 1) {
        int v = (t >= off) ? s[t - off] : 0;
        __syncthreads();
        s[t] += v;
        __syncthreads();
    }
    int excl = s[t] - c;
    g_offset[t] = excl;
    g_cursor[t] = excl;
}

// ---------------- scatter (b,k) pairs into per-parent buckets ----------------
__global__ void k_scatter() {
    int i = blockIdx.x * 256 + threadIdx.x;
    int p = g_topidx[i];
    int pos = atomicAdd(&g_cursor[p], 1);
    g_pairs[pos] = i;
}

// ---------------- G[p][c][d] = sum_s Wce[p][c][s] * Wdown[p][s][d] ----------------
// block: (p, d0=by*128). tile [32c x 128d]. 256 thr: dq=(tid>>3)*4, c0=(tid&7)*4.
__global__ void __launch_bounds__(256) k_precompG(const float* __restrict__ Wdown,
                                                  const float* __restrict__ Wce) {
    __shared__ float Wd[SS][132];   // [s][d] (rows 16B-aligned: 132*4=528)
    __shared__ float Ce[SS][36];    // [s][c]
    const int p = blockIdx.x;
    const int d0 = blockIdx.y * 128;
    const int tid = threadIdx.x;

    // load Wdown tile [64 s][128 d] directly (already s-major rows over d)
    for (int l = tid; l < SS * 32; l += 256) {           // 32 float4 per row
        int s = l >> 5, q = l & 31;
        *(float4*)&Wd[s][q * 4] =
            *(const float4*)&Wdown[((size_t)p * SS + s) * DD + d0 + q * 4];
    }
    // load Wce [32 c][64 s] transposed into Ce[s][c]
    for (int l = tid; l < CC * 16; l += 256) {           // 16 float4 per c-row
        int c = l >> 4, sq = l & 15;
        float4 v = *(const float4*)&Wce[((size_t)p * CC + c) * SS + sq * 4];
        Ce[sq * 4 + 0][c] = v.x;
        Ce[sq * 4 + 1][c] = v.y;
        Ce[sq * 4 + 2][c] = v.z;
        Ce[sq * 4 + 3][c] = v.w;
    }
    __syncthreads();

    const int dq = (tid >> 3) * 4;
    const int c0 = (tid & 7) * 4;
    float acc[4][4];                 // [d j][c i]
#pragma unroll
    for (int j = 0; j < 4; j++)
#pragma unroll
        for (int i = 0; i < 4; i++) acc[j][i] = 0.f;

#pragma unroll 4
    for (int s4 = 0; s4 < SS; s4 += 4) {
        float4 cd[4], wu[4];
#pragma unroll
        for (int u = 0; u < 4; u++) {
            cd[u] = *(const float4*)&Ce[s4 + u][c0];
            wu[u] = *(const float4*)&Wd[s4 + u][dq];
        }
#pragma unroll
        for (int u = 0; u < 4; u++) {
            acc[0][0] += wu[u].x * cd[u].x; acc[0][1] += wu[u].x * cd[u].y;
            acc[0][2] += wu[u].x * cd[u].z; acc[0][3] += wu[u].x * cd[u].w;
            acc[1][0] += wu[u].y * cd[u].x; acc[1][1] += wu[u].y * cd[u].y;
            acc[1][2] += wu[u].y * cd[u].z; acc[1][3] += wu[u].y * cd[u].w;
            acc[2][0] += wu[u].z * cd[u].x; acc[2][1] += wu[u].z * cd[u].y;
            acc[2][2] += wu[u].z * cd[u].z; acc[2][3] += wu[u].z * cd[u].w;
            acc[3][0] += wu[u].w * cd[u].x; acc[3][1] += wu[u].w * cd[u].y;
            acc[3][2] += wu[u].w * cd[u].z; acc[3][3] += wu[u].w * cd[u].w;
        }
    }
#pragma unroll
    for (int i = 0; i < 4; i++) {
        float4 o = make_float4(acc[0][i], acc[1][i], acc[2][i], acc[3][i]);
        *(float4*)&g_G[((size_t)p * CC + c0 + i) * DD + d0 + dq] = o;
    }
}

// ---------------- M'[p][c][d] = sum_s Wup[p][d][s]*Wcd[p][s][c] + 0.1*Wrd[d][p] ----------------
__global__ void __launch_bounds__(256) k_precompM(const float* __restrict__ Wup,
                                                  const float* __restrict__ Wcd,
                                                  const float* __restrict__ Wrd) {
    __shared__ float Wu[SS][132];   // [s][d]  (transposed from global [d][s])
    __shared__ float Cd[SS][36];    // [s][c]
    const int p = blockIdx.x;
    const int d0 = blockIdx.y * 128;
    const int tid = threadIdx.x;

    // Wup [128 d][64 s] -> Wu[s][d] (transpose in smem)
    for (int l = tid; l < 128 * 16; l += 256) {          // 16 float4 per d-row
        int d = l >> 4, sq = l & 15;
        float4 v = *(const float4*)&Wup[((size_t)p * DD + d0 + d) * SS + sq * 4];
        Wu[sq * 4 + 0][d] = v.x;
        Wu[sq * 4 + 1][d] = v.y;
        Wu[sq * 4 + 2][d] = v.z;
        Wu[sq * 4 + 3][d] = v.w;
    }
    // Wcd [64 s][32 c] direct
    for (int l = tid; l < SS * 8; l += 256) {            // 8 float4 per s-row
        int s = l >> 3, q = l & 7;
        *(float4*)&Cd[s][q * 4] =
            *(const float4*)&Wcd[((size_t)p * SS + s) * CC + q * 4];
    }
    __syncthreads();

    const int dq = (tid >> 3) * 4;
    const int c0 = (tid & 7) * 4;
    float acc[4][4];
#pragma unroll
    for (int j = 0; j < 4; j++)
#pragma unroll
        for (int i = 0; i < 4; i++) acc[j][i] = 0.f;

#pragma unroll 4
    for (int s4 = 0; s4 < SS; s4 += 4) {
        float4 cd[4], wu[4];
#pragma unroll
        for (int u = 0; u < 4; u++) {
            cd[u] = *(const float4*)&Cd[s4 + u][c0];
            wu[u] = *(const float4*)&Wu[s4 + u][dq];
        }
#pragma unroll
        for (int u = 0; u < 4; u++) {
            acc[0][0] += wu[u].x * cd[u].x; acc[0][1] += wu[u].x * cd[u].y;
            acc[0][2] += wu[u].x * cd[u].z; acc[0][3] += wu[u].x * cd[u].w;
            acc[1][0] += wu[u].y * cd[u].x; acc[1][1] += wu[u].y * cd[u].y;
            acc[1][2] += wu[u].y * cd[u].z; acc[1][3] += wu[u].y * cd[u].w;
            acc[2][0] += wu[u].z * cd[u].x; acc[2][1] += wu[u].z * cd[u].y;
            acc[2][2] += wu[u].z * cd[u].z; acc[2][3] += wu[u].z * cd[u].w;
            acc[3][0] += wu[u].w * cd[u].x; acc[3][1] += wu[u].w * cd[u].y;
            acc[3][2] += wu[u].w * cd[u].z; acc[3][3] += wu[u].w * cd[u].w;
        }
    }
    // fold 0.1 * W_rd column p
    float wr[4];
#pragma unroll
    for (int j = 0; j < 4; j++)
        wr[j] = 0.1f * Wrd[(size_t)(d0 + dq + j) * PP + p];
#pragma unroll
    for (int i = 0; i < 4; i++) {
        float4 o = make_float4(acc[0][i] + wr[0], acc[1][i] + wr[1],
                               acc[2][i] + wr[2], acc[3][i] + wr[3]);
        *(float4*)&g_M[((size_t)p * CC + c0 + i) * DD + d0 + dq] = o;
    }
}

// ---------------- per-parent child logits + argmax (G is [p][c][d]) ----------------
// grid (P, 2), 128 threads. tile 64 tok x 32 c. thread: tr=tid>>3 (tok), cg=tid&7 (c0=cg*4).
__global__ void __launch_bounds__(128) k_childlogits(const float* __restrict__ X,
                                                     const float* __restrict__ bce) {
    __shared__ float Xs[64][68];    // [t][d]
    __shared__ float Gs[32][68];    // [c][d]
    __shared__ int toks[64];
    const int p = blockIdx.x;
    const int base = g_offset[p];
    const int n = g_count[p];
    const int tid = threadIdx.x;
    const int cg = tid & 7;
    const int c0 = cg * 4;
    const int tr = tid >> 3;        // 0..15
    float bc[4];
#pragma unroll
    for (int i = 0; i < 4; i++) bc[i] = bce[p * CC + c0 + i];

    for (int t0 = blockIdx.y * 64; t0 < n; t0 += 128) {
        if (tid < 64) toks[tid] = (t0 + tid < n) ? g_pairs[base + t0 + tid] : -1;
        __syncthreads();

        float acc[4][4];            // [tok j][c i]
#pragma unroll
        for (int j = 0; j < 4; j++)
#pragma unroll
            for (int i = 0; i < 4; i++) acc[j][i] = 0.f;

        for (int d0 = 0; d0 < DD; d0 += 64) {
            // Gs: 32 rows x 64 d (coalesced from G[p][c][d])
            for (int l = tid; l < 32 * 16; l += 128) {
                int c = l >> 4, q = l & 15;
                *(float4*)&Gs[c][q * 4] =
                    *(const float4*)&g_G[((size_t)p * CC + c) * DD + d0 + q * 4];
            }
            // Xs: 64 rows x 64 d
            for (int l = tid; l < 64 * 16; l += 128) {
                int r = l >> 4, q = l & 15;
                int pi = toks[r];
                float4 v = make_float4(0.f, 0.f, 0.f, 0.f);
                if (pi >= 0)
                    v = *(const float4*)&X[(size_t)(pi >> 3) * DD + d0 + q * 4];
                *(float4*)&Xs[r][q * 4] = v;
            }
            __syncthreads();

#pragma unroll 4
            for (int d4 = 0; d4 < 64; d4 += 4) {
                float4 xv[4], gv[4];
#pragma unroll
                for (int j = 0; j < 4; j++) xv[j] = *(const float4*)&Xs[tr + 16 * j][d4];
#pragma unroll
                for (int i = 0; i < 4; i++) gv[i] = *(const float4*)&Gs[c0 + i][d4];
#pragma unroll
                for (int j = 0; j < 4; j++)
#pragma unroll
                    for (int i = 0; i < 4; i++)
                        acc[j][i] += xv[j].x * gv[i].x + xv[j].y * gv[i].y
                                   + xv[j].z * gv[i].z + xv[j].w * gv[i].w;
            }
            __syncthreads();
        }

        // argmax over 32 c per token (tie -> lower index)
#pragma unroll
        for (int j = 0; j < 4; j++) {
            float bv = acc[j][0] + bc[0];
            int bi = c0;
#pragma unroll
            for (int i = 1; i < 4; i++) {
                float v = acc[j][i] + bc[i];
                if (v > bv) { bv = v; bi = c0 + i; }
            }
#pragma unroll
            for (int off = 4; off >= 1; off >>= 1) {
                float ov = __shfl_down_sync(0xffffffffu, bv, off, 8);
                int   oi = __shfl_down_sync(0xffffffffu, bi, off, 8);
                if (ov > bv || (ov == bv && oi < bi)) { bv = ov; bi = oi; }
            }
            if (cg == 0) {
                int pi = toks[tr + 16 * j];
                if (pi >= 0) g_child[pi] = bi;
            }
        }
        __syncthreads();
    }
}

// ---------------- decode: out = bias + sum_k M'[p_k][c_k] ----------------
__global__ void k_decode(const float* __restrict__ dbias, float* __restrict__ out) {
    const int b = blockIdx.x;
    __shared__ int sp[KP], sc[KP];
    const int tid = threadIdx.x;
    if (tid < KP) {
        sp[tid] = g_topidx[b * KP + tid];
        sc[tid] = g_child[b * KP + tid];
    }
    __syncthreads();
    size_t rowbase[KP];
#pragma unroll
    for (int k = 0; k < KP; k++)
        rowbase[k] = ((size_t)sp[k] * CC + sc[k]) * DD;
#pragma unroll
    for (int it = 0; it < 2; it++) {
        int d = (tid + it * 256) * 4;
        float4 a = *(const float4*)&dbias[d];
#pragma unroll
        for (int k = 0; k < KP; k++) {
            float4 m = *(const float4*)&g_M[rowbase[k] + d];
            a.x += m.x; a.y += m.y; a.z += m.z; a.w += m.w;
        }
        *(float4*)&out[(size_t)b * DD + d] = a;
    }
}

// ---------------- launch ----------------
extern "C" void kernel_launch(void* const* d_in, const int* in_sizes, int n_in,
                              void* d_out, int out_size) {
    const float* x      = (const float*)d_in[0];
    const float* W_re   = (const float*)d_in[1];
    const float* b_re   = (const float*)d_in[2];
    const float* W_rd   = (const float*)d_in[3];
    const float* W_down = (const float*)d_in[4];
    const float* W_up   = (const float*)d_in[5];
    const float* W_ce   = (const float*)d_in[6];
    const float* b_ce   = (const float*)d_in[7];
    const float* W_cd   = (const float*)d_in[8];
    const float* dbias  = (const float*)d_in[9];
    float* out = (float*)d_out;

    k_zero<<<1, 256>>>();
    k_gemm_logits<<<dim3(PP / 64, BB / 64), 256>>>(x, W_re, b_re);
    k_precompG<<<dim3(PP, DD / 128), 256>>>(W_down, W_ce);
    k_precompM<<<dim3(PP, DD / 128), 256>>>(W_up, W_cd, W_rd);
    k_topk<<<(BB * 32) / 256, 256>>>();
    k_scan<<<1, 256>>>();
    k_scatter<<<(BB * KP) / 256, 256>>>();
    k_childlogits<<<dim3(PP, 2), 128>>>(x, b_ce);
    k_decode<<<BB, 256>>>(dbias, out);
}